// round 8
// baseline (speedup 1.0000x reference)
#include <cuda_runtime.h>
#include <cuda_bf16.h>

#define N_NODES 50000
#define N_EDGES 800000
#define N_FEAT  500
#define N_HID   256
#define DCAT    512   // fused hidden width (2 branches x 256)
#define N_CLASS 10
#define MPAD    50048 // 391 * 128, padded row count for GEMM1
#define KPAD    512   // padded K for GEMM1

// ---------------- device scratch (static; no allocations allowed) -------------
__device__ int   g_is64;
__device__ int   g_counts[N_NODES];
__device__ int   g_row_start[N_NODES + 1];
__device__ int   g_cursor[N_NODES];
__device__ int   g_blockSums[256];
__device__ int   g_blockOffs[256];
__device__ int   g_col[N_EDGES];
__device__ float g_w[N_EDGES];
__device__ __align__(16) __nv_bfloat16 g_xh[(size_t)MPAD * KPAD];
__device__ __align__(16) __nv_bfloat16 g_xl[(size_t)MPAD * KPAD];
__device__ __align__(16) __nv_bfloat16 g_whT[DCAT * KPAD];  // [n][k]
__device__ __align__(16) __nv_bfloat16 g_wlT[DCAT * KPAD];  // [n][k]
__device__ float g_bcat[DCAT];
__device__ __align__(16) float g_y[(size_t)MPAD * DCAT];    // x@W1cat + b1cat
__device__ float g_z[(size_t)N_NODES * 20];                 // [z1(10)|z2(10)] per node

// ---------------- dtype detect ------------------------------------------------
__global__ void k_detect(const int* __restrict__ ei32) {
    if (threadIdx.x == 0) {
        int odd_nonzero = 0;
        for (int i = 0; i < 64; i++) odd_nonzero |= ei32[2 * i + 1];
        g_is64 = (odd_nonzero == 0) ? 1 : 0;
    }
}
__device__ __forceinline__ int edge_row(const int* ei32, int e, int is64) {
    return is64 ? ei32[2 * e] : ei32[e];
}
__device__ __forceinline__ int edge_col(const int* ei32, int e, int is64) {
    return is64 ? ei32[2 * (N_EDGES + e)] : ei32[N_EDGES + e];
}

// ---------------- CSR build ---------------------------------------------------
__global__ void k_zero() {
    int i = blockIdx.x * blockDim.x + threadIdx.x;
    if (i < N_NODES) { g_counts[i] = 0; g_cursor[i] = 0; }
}

__global__ void k_hist(const int* __restrict__ ei32) {
    int e = blockIdx.x * blockDim.x + threadIdx.x;
    if (e < N_EDGES) {
        int r = edge_row(ei32, e, g_is64);
        if ((unsigned)r < N_NODES) atomicAdd(&g_counts[r], 1);
    }
}

// parallel scan: (1) per-block reduce, (2) scan block sums, (3) block scan + offset
__global__ void k_scan1() {
    __shared__ int sm[256];
    int i = blockIdx.x * 256 + threadIdx.x;
    sm[threadIdx.x] = (i < N_NODES) ? g_counts[i] : 0;
    __syncthreads();
    for (int off = 128; off; off >>= 1) {
        if (threadIdx.x < off) sm[threadIdx.x] += sm[threadIdx.x + off];
        __syncthreads();
    }
    if (threadIdx.x == 0) g_blockSums[blockIdx.x] = sm[0];
}

__global__ void k_scan2(int nblocks) {
    __shared__ int sm[256];
    int v = (threadIdx.x < nblocks) ? g_blockSums[threadIdx.x] : 0;
    sm[threadIdx.x] = v;
    __syncthreads();
    for (int off = 1; off < 256; off <<= 1) {
        int t = (threadIdx.x >= off) ? sm[threadIdx.x - off] : 0;
        __syncthreads();
        sm[threadIdx.x] += t;
        __syncthreads();
    }
    if (threadIdx.x < nblocks) g_blockOffs[threadIdx.x] = sm[threadIdx.x] - v;
    if (threadIdx.x == 255) g_row_start[N_NODES] = sm[255];
}

__global__ void k_scan3() {
    __shared__ int sm[256];
    int i = blockIdx.x * 256 + threadIdx.x;
    int v = (i < N_NODES) ? g_counts[i] : 0;
    sm[threadIdx.x] = v;
    __syncthreads();
    for (int off = 1; off < 256; off <<= 1) {
        int t = (threadIdx.x >= off) ? sm[threadIdx.x - off] : 0;
        __syncthreads();
        sm[threadIdx.x] += t;
        __syncthreads();
    }
    if (i < N_NODES) g_row_start[i] = g_blockOffs[blockIdx.x] + sm[threadIdx.x] - v;
}

__global__ void k_scatter(const int* __restrict__ ei32,
                          const float* __restrict__ ew) {
    int e = blockIdx.x * blockDim.x + threadIdx.x;
    if (e < N_EDGES) {
        int is64 = g_is64;
        int r = edge_row(ei32, e, is64);
        int c = edge_col(ei32, e, is64);
        if ((unsigned)r < N_NODES && (unsigned)c < N_NODES) {
            int p = g_row_start[r] + atomicAdd(&g_cursor[r], 1);
            g_col[p] = c;
            g_w[p]   = ew[e];
        }
    }
}

// ---------------- split-precision prep ----------------------------------------
__global__ void k_prep_x(const float* __restrict__ x) {
    int t  = blockIdx.x * 256 + threadIdx.x;
    int r  = t >> 7;
    int c0 = (t & 127) * 4;
    if (r >= MPAD) return;
    float4 v = make_float4(0.f, 0.f, 0.f, 0.f);
    if (r < N_NODES && c0 < N_FEAT)
        v = *(const float4*)(x + (size_t)r * N_FEAT + c0);
    float vv[4] = {v.x, v.y, v.z, v.w};
    __nv_bfloat16 h[4], l[4];
#pragma unroll
    for (int i = 0; i < 4; i++) {
        h[i] = __float2bfloat16(vv[i]);
        l[i] = __float2bfloat16(vv[i] - __bfloat162float(h[i]));
    }
    *(uint2*)(g_xh + (size_t)r * KPAD + c0) = *(uint2*)h;
    *(uint2*)(g_xl + (size_t)r * KPAD + c0) = *(uint2*)l;
}

__global__ void k_prep_w(const float* __restrict__ W1a, const float* __restrict__ b1a,
                         const float* __restrict__ W1b, const float* __restrict__ b1b) {
    int t = blockIdx.x * 256 + threadIdx.x;  // over DCAT*KPAD
    if (t >= DCAT * KPAD) return;
    int n = t >> 9, k = t & 511;
    float v = 0.f;
    if (k < N_FEAT)
        v = (n < N_HID) ? W1a[k * N_HID + n] : W1b[k * N_HID + (n - N_HID)];
    __nv_bfloat16 h = __float2bfloat16(v);
    g_whT[n * KPAD + k] = h;
    g_wlT[n * KPAD + k] = __float2bfloat16(v - __bfloat162float(h));
    if (t < DCAT) g_bcat[t] = (t < N_HID) ? b1a[t] : b1b[t - N_HID];
}

// ---------------- GEMM1 (tensor cores, bf16 split precision) ------------------
#define BM 128
#define BN 128
#define BK 16
#define PITCH 24  // bf16 elements per smem row (48B: 16B-aligned, conflict-free frags)

__device__ __forceinline__ void mma16816(float* c, const unsigned* a, const unsigned* b) {
    asm volatile(
        "mma.sync.aligned.m16n8k16.row.col.f32.bf16.bf16.f32 "
        "{%0,%1,%2,%3}, {%4,%5,%6,%7}, {%8,%9}, {%0,%1,%2,%3};\n"
        : "+f"(c[0]), "+f"(c[1]), "+f"(c[2]), "+f"(c[3])
        : "r"(a[0]), "r"(a[1]), "r"(a[2]), "r"(a[3]), "r"(b[0]), "r"(b[1]));
}

__global__ void __launch_bounds__(256) k_gemm1_mma() {
    __shared__ __align__(16) __nv_bfloat16 sAh[2][BM * PITCH];
    __shared__ __align__(16) __nv_bfloat16 sAl[2][BM * PITCH];
    __shared__ __align__(16) __nv_bfloat16 sBh[2][BN * PITCH];
    __shared__ __align__(16) __nv_bfloat16 sBl[2][BN * PITCH];

    const int tid  = threadIdx.x;
    const int bm   = blockIdx.y * BM;
    const int bn   = blockIdx.x * BN;
    const int wid  = tid >> 5, lane = tid & 31;
    const int wm   = wid & 1, wn = wid >> 1;   // 2x4 warps -> 64x32 warp tiles
    const int mw   = wm * 64, nw = wn * 32;
    const int gid  = lane >> 2;                // 0..7
    const int tk4  = lane & 3;                 // 0..3

    const int lr = tid >> 1;
    const int lk = (tid & 1) * 8;
    const size_t aoff = (size_t)(bm + lr) * KPAD + lk;
    const size_t boff = (size_t)(bn + lr) * KPAD + lk;
    const int soff = lr * PITCH + lk;

    float acc[16][4];
#pragma unroll
    for (int i = 0; i < 16; i++)
#pragma unroll
        for (int j = 0; j < 4; j++) acc[i][j] = 0.f;

    {
        *(uint4*)&sAh[0][soff] = *(const uint4*)(g_xh + aoff);
        *(uint4*)&sAl[0][soff] = *(const uint4*)(g_xl + aoff);
        *(uint4*)&sBh[0][soff] = *(const uint4*)(g_whT + boff);
        *(uint4*)&sBl[0][soff] = *(const uint4*)(g_wlT + boff);
    }
    __syncthreads();

    const int NSTAGE = KPAD / BK;  // 32
    for (int s = 0; s < NSTAGE; s++) {
        const int cur = s & 1, nxt = cur ^ 1;
        uint4 pAh, pAl, pBh, pBl;
        if (s + 1 < NSTAGE) {
            int k0 = (s + 1) * BK;
            pAh = *(const uint4*)(g_xh + aoff + k0);
            pAl = *(const uint4*)(g_xl + aoff + k0);
            pBh = *(const uint4*)(g_whT + boff + k0);
            pBl = *(const uint4*)(g_wlT + boff + k0);
        }

        unsigned Ah[4][4], Al[4][4], Bh[4][2], Bl[4][2];
#pragma unroll
        for (int ni = 0; ni < 4; ni++) {
            int n = nw + ni * 8 + gid;
            Bh[ni][0] = *(const unsigned*)&sBh[cur][n * PITCH + tk4 * 2];
            Bh[ni][1] = *(const unsigned*)&sBh[cur][n * PITCH + tk4 * 2 + 8];
            Bl[ni][0] = *(const unsigned*)&sBl[cur][n * PITCH + tk4 * 2];
            Bl[ni][1] = *(const unsigned*)&sBl[cur][n * PITCH + tk4 * 2 + 8];
        }
#pragma unroll
        for (int mi = 0; mi < 4; mi++) {
            int m = mw + mi * 16 + gid;
            Ah[mi][0] = *(const unsigned*)&sAh[cur][m * PITCH + tk4 * 2];
            Ah[mi][1] = *(const unsigned*)&sAh[cur][(m + 8) * PITCH + tk4 * 2];
            Ah[mi][2] = *(const unsigned*)&sAh[cur][m * PITCH + tk4 * 2 + 8];
            Ah[mi][3] = *(const unsigned*)&sAh[cur][(m + 8) * PITCH + tk4 * 2 + 8];
            Al[mi][0] = *(const unsigned*)&sAl[cur][m * PITCH + tk4 * 2];
            Al[mi][1] = *(const unsigned*)&sAl[cur][(m + 8) * PITCH + tk4 * 2];
            Al[mi][2] = *(const unsigned*)&sAl[cur][m * PITCH + tk4 * 2 + 8];
            Al[mi][3] = *(const unsigned*)&sAl[cur][(m + 8) * PITCH + tk4 * 2 + 8];
        }
#pragma unroll
        for (int mi = 0; mi < 4; mi++)
#pragma unroll
            for (int ni = 0; ni < 4; ni++) {
                mma16816(acc[mi * 4 + ni], Ah[mi], Bh[ni]);
                mma16816(acc[mi * 4 + ni], Ah[mi], Bl[ni]);
                mma16816(acc[mi * 4 + ni], Al[mi], Bh[ni]);
            }

        if (s + 1 < NSTAGE) {
            *(uint4*)&sAh[nxt][soff] = pAh;
            *(uint4*)&sAl[nxt][soff] = pAl;
            *(uint4*)&sBh[nxt][soff] = pBh;
            *(uint4*)&sBl[nxt][soff] = pBl;
        }
        __syncthreads();
    }

#pragma unroll
    for (int mi = 0; mi < 4; mi++) {
#pragma unroll
        for (int ni = 0; ni < 4; ni++) {
            int r = bm + mw + mi * 16 + gid;
            int c = bn + nw + ni * 8 + tk4 * 2;
            float b0 = g_bcat[c], b1 = g_bcat[c + 1];
            float* acc4 = acc[mi * 4 + ni];
            float2 v0 = make_float2(acc4[0] + b0, acc4[1] + b1);
            float2 v1 = make_float2(acc4[2] + b0, acc4[3] + b1);
            *(float2*)&g_y[(size_t)r * DCAT + c] = v0;
            *(float2*)&g_y[(size_t)(r + 8) * DCAT + c] = v1;
        }
    }
}

// ---- Fused SpMM1 + ReLU + GEMM2:  z[row] = relu(A y)[row] @ W2cat + b2cat ----
// Block = 128 threads; thread tid owns dims d = tid*4 .. tid*4+3.
// Warps 0,1 hold branch-1 dims (d<256); warps 2,3 hold branch-2 dims.
// W2 slice (4 rows x 10 cols) lives in registers; loaded once per block.
#define FUSE_BLOCKS 2048
__global__ void __launch_bounds__(128) k_spmm1_fused(
    const float* __restrict__ W2a, const float* __restrict__ b2a,
    const float* __restrict__ W2b, const float* __restrict__ b2b)
{
    __shared__ float sred[4][10];
    const int tid  = threadIdx.x;
    const int wid  = tid >> 5;
    const int lane = tid & 31;
    const int d    = tid * 4;

    // register-resident W2 slice: rows d..d+3 of the owning branch
    float w2[4][10];
    {
        const float* Wsrc = (d < N_HID) ? (W2a + d * 10) : (W2b + (d - N_HID) * 10);
#pragma unroll
        for (int i = 0; i < 4; i++)
#pragma unroll
            for (int c = 0; c < 10; c++) w2[i][c] = Wsrc[i * 10 + c];
    }
    // bias for the final store (warp 0, lanes 0..19)
    float bias = 0.f;
    if (wid == 0) {
        if (lane < 10)      bias = b2a[lane];
        else if (lane < 20) bias = b2b[lane - 10];
    }

    for (int row = blockIdx.x; row < N_NODES; row += FUSE_BLOCKS) {
        int s = g_row_start[row], t = g_row_start[row + 1];
        float ax = 0.f, ay = 0.f, az = 0.f, aw = 0.f;
        for (int e = s; e < t; e++) {
            int   c = __ldg(&g_col[e]);
            float w = __ldg(&g_w[e]);
            float4 v = *(const float4*)&g_y[(size_t)c * DCAT + d];
            ax += w * v.x; ay += w * v.y; az += w * v.z; aw += w * v.w;
        }
        ax = fmaxf(ax, 0.f); ay = fmaxf(ay, 0.f);
        az = fmaxf(az, 0.f); aw = fmaxf(aw, 0.f);

        // per-thread partial z (10 cols of the owning branch)
        float p[10];
#pragma unroll
        for (int c = 0; c < 10; c++)
            p[c] = ax * w2[0][c] + ay * w2[1][c] + az * w2[2][c] + aw * w2[3][c];

        // warp butterfly reduce (all lanes end with warp sum)
#pragma unroll
        for (int c = 0; c < 10; c++) {
            float v = p[c];
            v += __shfl_xor_sync(0xffffffffu, v, 16);
            v += __shfl_xor_sync(0xffffffffu, v, 8);
            v += __shfl_xor_sync(0xffffffffu, v, 4);
            v += __shfl_xor_sync(0xffffffffu, v, 2);
            v += __shfl_xor_sync(0xffffffffu, v, 1);
            p[c] = v;
        }
        if (lane < 10) sred[wid][lane] = p[lane];
        __syncthreads();
        if (wid == 0 && lane < 20) {
            float v = (lane < 10) ? (sred[0][lane] + sred[1][lane])
                                  : (sred[2][lane - 10] + sred[3][lane - 10]);
            g_z[(size_t)row * 20 + lane] = v + bias;
        }
        __syncthreads();
    }
}

// ---------------- SpMM2: out[br][row][c] = sum_e w * z[col][br*10+c] ----------
// 320 threads = 16 rows x 20 lanes
__global__ void __launch_bounds__(320) k_spmm2(float* __restrict__ out) {
    int t    = threadIdx.x;
    int row  = blockIdx.x * 16 + t / 20;
    int c20  = t % 20;
    if (row >= N_NODES) return;
    int s = g_row_start[row], tend = g_row_start[row + 1];
    float acc = 0.f;
    for (int e = s; e < tend; e++) {
        int   c = __ldg(&g_col[e]);
        float w = __ldg(&g_w[e]);
        acc += w * g_z[(size_t)c * 20 + c20];
    }
    int br = c20 / 10, cc = c20 % 10;
    out[(size_t)br * (N_NODES * N_CLASS) + (size_t)row * N_CLASS + cc] = acc;
}

// ---------------- launch ------------------------------------------------------
extern "C" void kernel_launch(void* const* d_in, const int* in_sizes, int n_in,
                              void* d_out, int out_size)
{
    const float* x   = (const float*)d_in[0];
    const int*   ei  = (const int*)d_in[1];
    const float* ew  = (const float*)d_in[2];
    const float* W1a = (const float*)d_in[3];
    const float* b1a = (const float*)d_in[4];
    const float* W2a = (const float*)d_in[5];
    const float* b2a = (const float*)d_in[6];
    const float* W1b = (const float*)d_in[7];
    const float* b1b = (const float*)d_in[8];
    const float* W2b = (const float*)d_in[9];
    const float* b2b = (const float*)d_in[10];
    float* out = (float*)d_out;

    const int SCAN_BLOCKS = (N_NODES + 255) / 256;  // 196

    k_detect<<<1, 32>>>(ei);
    k_zero<<<(N_NODES + 255) / 256, 256>>>();
    k_hist<<<(N_EDGES + 255) / 256, 256>>>(ei);
    k_scan1<<<SCAN_BLOCKS, 256>>>();
    k_scan2<<<1, 256>>>(SCAN_BLOCKS);
    k_scan3<<<SCAN_BLOCKS, 256>>>();
    k_scatter<<<(N_EDGES + 255) / 256, 256>>>(ei, ew);
    k_prep_x<<<(MPAD * 128 + 255) / 256, 256>>>(x);
    k_prep_w<<<(DCAT * KPAD + 255) / 256, 256>>>(W1a, b1a, W1b, b1b);
    k_gemm1_mma<<<dim3(DCAT / BN, MPAD / BM), 256>>>();
    k_spmm1_fused<<<FUSE_BLOCKS, 128>>>(W2a, b2a, W2b, b2b);
    k_spmm2<<<(N_NODES + 15) / 16, 320>>>(out);
}

// round 11
// speedup vs baseline: 1.1354x; 1.1354x over previous
#include <cuda_runtime.h>
#include <cuda_bf16.h>
#include <cstdint>

#define N_NODES 50000
#define N_EDGES 800000
#define N_FEAT  500
#define N_HID   256
#define DCAT    512   // fused hidden width (2 branches x 256)
#define N_CLASS 10
#define MPAD    50048 // 391 * 128
#define KPAD    512

// ---------------- device scratch ----------------------------------------------
__device__ int   g_is64;
__device__ int   g_counts[N_NODES];
__device__ int   g_row_start[N_NODES + 1];
__device__ int   g_cursor[N_NODES];
__device__ int   g_blockSums[256];
__device__ int   g_blockOffs[256];
__device__ int   g_col[N_EDGES];
__device__ float g_w[N_EDGES];
__device__ __align__(16) __nv_bfloat16 g_xh[(size_t)MPAD * KPAD];
__device__ __align__(16) __nv_bfloat16 g_xl[(size_t)MPAD * KPAD];
__device__ __align__(16) __nv_bfloat16 g_whT[DCAT * KPAD];  // [n][k]
__device__ __align__(16) __nv_bfloat16 g_wlT[DCAT * KPAD];  // [n][k]
__device__ float g_bcat[DCAT];
__device__ __align__(16) float g_y[(size_t)MPAD * DCAT];
__device__ __align__(16) float g_g[(size_t)N_NODES * DCAT];
__device__ float g_z[(size_t)N_NODES * 20];

#define CP_ASYNC16(dst, src) \
    asm volatile("cp.async.cg.shared.global [%0], [%1], 16;" :: "r"(dst), "l"(src))
#define CP_COMMIT() asm volatile("cp.async.commit_group;" ::: "memory")
#define CP_WAIT0()  asm volatile("cp.async.wait_group 0;" ::: "memory")

__device__ __forceinline__ uint32_t smem_u32(const void* p) {
    uint32_t a;
    asm("{ .reg .u64 t; cvta.to.shared.u64 t, %1; cvt.u32.u64 %0, t; }" : "=r"(a) : "l"(p));
    return a;
}

// ---------------- dtype detect ------------------------------------------------
__global__ void k_detect(const int* __restrict__ ei32) {
    if (threadIdx.x == 0) {
        int odd_nonzero = 0;
        for (int i = 0; i < 64; i++) odd_nonzero |= ei32[2 * i + 1];
        g_is64 = (odd_nonzero == 0) ? 1 : 0;
    }
}
__device__ __forceinline__ int edge_row(const int* ei32, int e, int is64) {
    return is64 ? ei32[2 * e] : ei32[e];
}
__device__ __forceinline__ int edge_col(const int* ei32, int e, int is64) {
    return is64 ? ei32[2 * (N_EDGES + e)] : ei32[N_EDGES + e];
}

// ---------------- CSR build ---------------------------------------------------
__global__ void k_zero() {
    int i = blockIdx.x * blockDim.x + threadIdx.x;
    if (i < N_NODES) { g_counts[i] = 0; g_cursor[i] = 0; }
}
__global__ void k_hist(const int* __restrict__ ei32) {
    int e = blockIdx.x * blockDim.x + threadIdx.x;
    if (e < N_EDGES) {
        int r = edge_row(ei32, e, g_is64);
        if ((unsigned)r < N_NODES) atomicAdd(&g_counts[r], 1);
    }
}
__global__ void k_scan1() {
    __shared__ int sm[256];
    int i = blockIdx.x * 256 + threadIdx.x;
    sm[threadIdx.x] = (i < N_NODES) ? g_counts[i] : 0;
    __syncthreads();
    for (int off = 128; off; off >>= 1) {
        if (threadIdx.x < off) sm[threadIdx.x] += sm[threadIdx.x + off];
        __syncthreads();
    }
    if (threadIdx.x == 0) g_blockSums[blockIdx.x] = sm[0];
}
__global__ void k_scan2(int nblocks) {
    __shared__ int sm[256];
    int v = (threadIdx.x < nblocks) ? g_blockSums[threadIdx.x] : 0;
    sm[threadIdx.x] = v;
    __syncthreads();
    for (int off = 1; off < 256; off <<= 1) {
        int t = (threadIdx.x >= off) ? sm[threadIdx.x - off] : 0;
        __syncthreads();
        sm[threadIdx.x] += t;
        __syncthreads();
    }
    if (threadIdx.x < nblocks) g_blockOffs[threadIdx.x] = sm[threadIdx.x] - v;
    if (threadIdx.x == 255) g_row_start[N_NODES] = sm[255];
}
__global__ void k_scan3() {
    __shared__ int sm[256];
    int i = blockIdx.x * 256 + threadIdx.x;
    int v = (i < N_NODES) ? g_counts[i] : 0;
    sm[threadIdx.x] = v;
    __syncthreads();
    for (int off = 1; off < 256; off <<= 1) {
        int t = (threadIdx.x >= off) ? sm[threadIdx.x - off] : 0;
        __syncthreads();
        sm[threadIdx.x] += t;
        __syncthreads();
    }
    if (i < N_NODES) g_row_start[i] = g_blockOffs[blockIdx.x] + sm[threadIdx.x] - v;
}
__global__ void k_scatter(const int* __restrict__ ei32, const float* __restrict__ ew) {
    int e = blockIdx.x * blockDim.x + threadIdx.x;
    if (e < N_EDGES) {
        int is64 = g_is64;
        int r = edge_row(ei32, e, is64);
        int c = edge_col(ei32, e, is64);
        if ((unsigned)r < N_NODES && (unsigned)c < N_NODES) {
            int p = g_row_start[r] + atomicAdd(&g_cursor[r], 1);
            g_col[p] = c;
            g_w[p]   = ew[e];
        }
    }
}

// ---------------- split-precision prep ----------------------------------------
__global__ void k_prep_x(const float* __restrict__ x) {
    int t  = blockIdx.x * 256 + threadIdx.x;
    int r  = t >> 7;
    int c0 = (t & 127) * 4;
    if (r >= MPAD) return;
    float4 v = make_float4(0.f, 0.f, 0.f, 0.f);
    if (r < N_NODES && c0 < N_FEAT)
        v = *(const float4*)(x + (size_t)r * N_FEAT + c0);
    float vv[4] = {v.x, v.y, v.z, v.w};
    __nv_bfloat16 h[4], l[4];
#pragma unroll
    for (int i = 0; i < 4; i++) {
        h[i] = __float2bfloat16(vv[i]);
        l[i] = __float2bfloat16(vv[i] - __bfloat162float(h[i]));
    }
    *(uint2*)(g_xh + (size_t)r * KPAD + c0) = *(uint2*)h;
    *(uint2*)(g_xl + (size_t)r * KPAD + c0) = *(uint2*)l;
}
__global__ void k_prep_w(const float* __restrict__ W1a, const float* __restrict__ b1a,
                         const float* __restrict__ W1b, const float* __restrict__ b1b) {
    int t = blockIdx.x * 256 + threadIdx.x;
    if (t >= DCAT * KPAD) return;
    int n = t >> 9, k = t & 511;
    float v = 0.f;
    if (k < N_FEAT)
        v = (n < N_HID) ? W1a[k * N_HID + n] : W1b[k * N_HID + (n - N_HID)];
    __nv_bfloat16 h = __float2bfloat16(v);
    g_whT[n * KPAD + k] = h;
    g_wlT[n * KPAD + k] = __float2bfloat16(v - __bfloat162float(h));
    if (t < DCAT) g_bcat[t] = (t < N_HID) ? b1a[t] : b1b[t - N_HID];
}

// ---------------- GEMM1 (mma.sync bf16 split precision, cp.async staging) -----
#define BM 128
#define BN 128
#define BK 16
#define PITCH 24  // bf16 elements per smem row (48B: 16B-aligned, conflict-free frags)

__device__ __forceinline__ void mma16816(float* c, const unsigned* a, const unsigned* b) {
    asm volatile(
        "mma.sync.aligned.m16n8k16.row.col.f32.bf16.bf16.f32 "
        "{%0,%1,%2,%3}, {%4,%5,%6,%7}, {%8,%9}, {%0,%1,%2,%3};\n"
        : "+f"(c[0]), "+f"(c[1]), "+f"(c[2]), "+f"(c[3])
        : "r"(a[0]), "r"(a[1]), "r"(a[2]), "r"(a[3]), "r"(b[0]), "r"(b[1]));
}

__global__ void __launch_bounds__(256, 2) k_gemm1_mma() {
    __shared__ __align__(16) __nv_bfloat16 sAh[2][BM * PITCH];
    __shared__ __align__(16) __nv_bfloat16 sAl[2][BM * PITCH];
    __shared__ __align__(16) __nv_bfloat16 sBh[2][BN * PITCH];
    __shared__ __align__(16) __nv_bfloat16 sBl[2][BN * PITCH];

    const int tid  = threadIdx.x;
    const int bm   = blockIdx.y * BM;
    const int bn   = blockIdx.x * BN;
    const int wid  = tid >> 5, lane = tid & 31;
    const int wm   = wid & 1, wn = wid >> 1;   // 2x4 warps -> 64x32 warp tiles
    const int mw   = wm * 64, nw = wn * 32;
    const int gid  = lane >> 2;                // 0..7
    const int tk4  = lane & 3;                 // 0..3

    // loader mapping: 256 threads, each one 16B cp.async per matrix per stage
    const int lr = tid >> 1;
    const int lk = (tid & 1) * 8;
    const size_t aoff = (size_t)(bm + lr) * KPAD + lk;
    const size_t boff = (size_t)(bn + lr) * KPAD + lk;
    const uint32_t sAh0 = smem_u32(&sAh[0][0]), sAl0 = smem_u32(&sAl[0][0]);
    const uint32_t sBh0 = smem_u32(&sBh[0][0]), sBl0 = smem_u32(&sBl[0][0]);
    const uint32_t soffB = (lr * PITCH + lk) * 2;          // byte offset in stage
    const uint32_t stageB = BM * PITCH * 2;                // bytes per stage

    float acc[16][4];
#pragma unroll
    for (int i = 0; i < 16; i++)
#pragma unroll
        for (int j = 0; j < 4; j++) acc[i][j] = 0.f;

    // prologue: stage 0 via cp.async
    CP_ASYNC16(sAh0 + soffB, g_xh + aoff);
    CP_ASYNC16(sAl0 + soffB, g_xl + aoff);
    CP_ASYNC16(sBh0 + soffB, g_whT + boff);
    CP_ASYNC16(sBl0 + soffB, g_wlT + boff);
    CP_COMMIT();
    CP_WAIT0();
    __syncthreads();

    const int NSTAGE = KPAD / BK;  // 32
    for (int s = 0; s < NSTAGE; s++) {
        const int cur = s & 1, nxt = cur ^ 1;
        if (s + 1 < NSTAGE) {
            int k0 = (s + 1) * BK;
            uint32_t so = nxt * stageB + soffB;
            CP_ASYNC16(sAh0 + so, g_xh + aoff + k0);
            CP_ASYNC16(sAl0 + so, g_xl + aoff + k0);
            CP_ASYNC16(sBh0 + so, g_whT + boff + k0);
            CP_ASYNC16(sBl0 + so, g_wlT + boff + k0);
            CP_COMMIT();
        }

        // fragment loads (verified layout, unchanged)
        unsigned Ah[4][4], Al[4][4], Bh[4][2], Bl[4][2];
#pragma unroll
        for (int ni = 0; ni < 4; ni++) {
            int n = nw + ni * 8 + gid;
            Bh[ni][0] = *(const unsigned*)&sBh[cur][n * PITCH + tk4 * 2];
            Bh[ni][1] = *(const unsigned*)&sBh[cur][n * PITCH + tk4 * 2 + 8];
            Bl[ni][0] = *(const unsigned*)&sBl[cur][n * PITCH + tk4 * 2];
            Bl[ni][1] = *(const unsigned*)&sBl[cur][n * PITCH + tk4 * 2 + 8];
        }
#pragma unroll
        for (int mi = 0; mi < 4; mi++) {
            int m = mw + mi * 16 + gid;
            Ah[mi][0] = *(const unsigned*)&sAh[cur][m * PITCH + tk4 * 2];
            Ah[mi][1] = *(const unsigned*)&sAh[cur][(m + 8) * PITCH + tk4 * 2];
            Ah[mi][2] = *(const unsigned*)&sAh[cur][m * PITCH + tk4 * 2 + 8];
            Ah[mi][3] = *(const unsigned*)&sAh[cur][(m + 8) * PITCH + tk4 * 2 + 8];
            Al[mi][0] = *(const unsigned*)&sAl[cur][m * PITCH + tk4 * 2];
            Al[mi][1] = *(const unsigned*)&sAl[cur][(m + 8) * PITCH + tk4 * 2];
            Al[mi][2] = *(const unsigned*)&sAl[cur][m * PITCH + tk4 * 2 + 8];
            Al[mi][3] = *(const unsigned*)&sAl[cur][(m + 8) * PITCH + tk4 * 2 + 8];
        }
#pragma unroll
        for (int mi = 0; mi < 4; mi++)
#pragma unroll
            for (int ni = 0; ni < 4; ni++) {
                mma16816(acc[mi * 4 + ni], Ah[mi], Bh[ni]);
                mma16816(acc[mi * 4 + ni], Ah[mi], Bl[ni]);
                mma16816(acc[mi * 4 + ni], Al[mi], Bh[ni]);
            }

        if (s + 1 < NSTAGE) CP_WAIT0();
        __syncthreads();
    }

    // epilogue: add bias, store fp32 (rows padded -> no guard)
#pragma unroll
    for (int mi = 0; mi < 4; mi++) {
#pragma unroll
        for (int ni = 0; ni < 4; ni++) {
            int r = bm + mw + mi * 16 + gid;
            int c = bn + nw + ni * 8 + tk4 * 2;
            float b0 = g_bcat[c], b1 = g_bcat[c + 1];
            float* acc4 = acc[mi * 4 + ni];
            float2 v0 = make_float2(acc4[0] + b0, acc4[1] + b1);
            float2 v1 = make_float2(acc4[2] + b0, acc4[3] + b1);
            *(float2*)&g_y[(size_t)r * DCAT + c] = v0;
            *(float2*)&g_y[(size_t)(r + 8) * DCAT + c] = v1;
        }
    }
}

// ---------------- SpMM1: g[row] = relu( sum_e w * y[col] ), D=512 -------------
__global__ void __launch_bounds__(128) k_spmm1() {
    int row = blockIdx.x;
    int s = g_row_start[row], t = g_row_start[row + 1];
    int d = threadIdx.x * 4;
    float ax = 0.f, ay = 0.f, az = 0.f, aw = 0.f;
    for (int e = s; e < t; e++) {
        int   c = __ldg(&g_col[e]);
        float w = __ldg(&g_w[e]);
        float4 v = *(const float4*)&g_y[(size_t)c * DCAT + d];
        ax += w * v.x; ay += w * v.y; az += w * v.z; aw += w * v.w;
    }
    float4 o;
    o.x = fmaxf(ax, 0.f); o.y = fmaxf(ay, 0.f);
    o.z = fmaxf(az, 0.f); o.w = fmaxf(aw, 0.f);
    *(float4*)&g_g[(size_t)row * DCAT + d] = o;
}

// ---------------- GEMM2 -------------------------------------------------------
__global__ void __launch_bounds__(256) k_gemm2(
    const float* __restrict__ W2a, const float* __restrict__ b2a,
    const float* __restrict__ W2b, const float* __restrict__ b2b)
{
    __shared__ float sW[DCAT * 10];
    for (int i = threadIdx.x; i < DCAT * 10; i += blockDim.x) {
        int d = i / 10, c = i % 10;
        sW[i] = (d < N_HID) ? W2a[d * 10 + c] : W2b[(d - N_HID) * 10 + c];
    }
    __syncthreads();

    int lane   = threadIdx.x & 31;
    int warp   = (blockIdx.x * blockDim.x + threadIdx.x) >> 5;
    int nwarps = (gridDim.x * blockDim.x) >> 5;

    for (int row = warp; row < N_NODES; row += nwarps) {
        float acc[20];
#pragma unroll
        for (int c = 0; c < 20; c++) acc[c] = 0.f;
        const float* grow = &g_g[(size_t)row * DCAT];
#pragma unroll
        for (int k = 0; k < 16; k++) {
            int d = lane + 32 * k;
            float gv = grow[d];
            const float* wrow = &sW[d * 10];
            float* ap = (k < 8) ? acc : acc + 10;
#pragma unroll
            for (int c = 0; c < 10; c++) ap[c] += gv * wrow[c];
        }
#pragma unroll
        for (int c = 0; c < 20; c++) {
            float v = acc[c];
            v += __shfl_xor_sync(0xffffffffu, v, 16);
            v += __shfl_xor_sync(0xffffffffu, v, 8);
            v += __shfl_xor_sync(0xffffffffu, v, 4);
            v += __shfl_xor_sync(0xffffffffu, v, 2);
            v += __shfl_xor_sync(0xffffffffu, v, 1);
            acc[c] = v;
        }
        if (lane == 0) {
#pragma unroll
            for (int c = 0; c < 10; c++) g_z[(size_t)row * 20 + c]      = acc[c]      + b2a[c];
#pragma unroll
            for (int c = 0; c < 10; c++) g_z[(size_t)row * 20 + 10 + c] = acc[10 + c] + b2b[c];
        }
    }
}

// ---------------- SpMM2: 320 threads = 16 rows x 20 lanes ---------------------
__global__ void __launch_bounds__(320) k_spmm2(float* __restrict__ out) {
    int t    = threadIdx.x;
    int row  = blockIdx.x * 16 + t / 20;
    int c20  = t % 20;
    if (row >= N_NODES) return;
    int s = g_row_start[row], tend = g_row_start[row + 1];
    float acc = 0.f;
    for (int e = s; e < tend; e++) {
        int   c = __ldg(&g_col[e]);
        float w = __ldg(&g_w[e]);
        acc += w * g_z[(size_t)c * 20 + c20];
    }
    int br = c20 / 10, cc = c20 % 10;
    out[(size_t)br * (N_NODES * N_CLASS) + (size_t)row * N_CLASS + cc] = acc;
}

// ---------------- launch ------------------------------------------------------
extern "C" void kernel_launch(void* const* d_in, const int* in_sizes, int n_in,
                              void* d_out, int out_size)
{
    const float* x   = (const float*)d_in[0];
    const int*   ei  = (const int*)d_in[1];
    const float* ew  = (const float*)d_in[2];
    const float* W1a = (const float*)d_in[3];
    const float* b1a = (const float*)d_in[4];
    const float* W2a = (const float*)d_in[5];
    const float* b2a = (const float*)d_in[6];
    const float* W1b = (const float*)d_in[7];
    const float* b1b = (const float*)d_in[8];
    const float* W2b = (const float*)d_in[9];
    const float* b2b = (const float*)d_in[10];
    float* out = (float*)d_out;

    const int SCAN_BLOCKS = (N_NODES + 255) / 256;  // 196

    k_detect<<<1, 32>>>(ei);
    k_zero<<<(N_NODES + 255) / 256, 256>>>();
    k_hist<<<(N_EDGES + 255) / 256, 256>>>(ei);
    k_scan1<<<SCAN_BLOCKS, 256>>>();
    k_scan2<<<1, 256>>>(SCAN_BLOCKS);
    k_scan3<<<SCAN_BLOCKS, 256>>>();
    k_scatter<<<(N_EDGES + 255) / 256, 256>>>(ei, ew);
    k_prep_x<<<(MPAD * 128 + 255) / 256, 256>>>(x);
    k_prep_w<<<(DCAT * KPAD + 255) / 256, 256>>>(W1a, b1a, W1b, b1b);
    k_gemm1_mma<<<dim3(DCAT / BN, MPAD / BM), 256>>>();
    k_spmm1<<<N_NODES, 128>>>();
    k_gemm2<<<782, 256>>>(W2a, b2a, W2b, b2b);
    k_spmm2<<<(N_NODES + 15) / 16, 320>>>(out);
}

// round 12
// speedup vs baseline: 1.5259x; 1.3439x over previous
#include <cuda_runtime.h>
#include <cuda_fp16.h>
#include <cstdint>

#define N_NODES 50000
#define N_EDGES 800000
#define N_FEAT  500
#define N_HID   256
#define DCAT    512   // fused hidden width (2 branches x 256)
#define N_CLASS 10
#define MPAD    50048 // 391 * 128
#define KPAD    512

// ---------------- device scratch ----------------------------------------------
__device__ int   g_is64;
__device__ int   g_counts[N_NODES];
__device__ int   g_row_start[N_NODES + 1];
__device__ int   g_cursor[N_NODES];
__device__ int   g_blockSums[256];
__device__ int   g_blockOffs[256];
__device__ int   g_col[N_EDGES];
__device__ float g_w[N_EDGES];
__device__ __align__(16) __half g_xh[(size_t)MPAD * KPAD];   // fp16(x)
__device__ __align__(16) __half g_whT[DCAT * KPAD];          // [n][k] fp16(w)
__device__ __align__(16) __half g_wlT[DCAT * KPAD];          // [n][k] w - fp16(w)
__device__ float g_bcat[DCAT];
__device__ __align__(16) __half g_yh[(size_t)MPAD * DCAT];   // y in fp16
__device__ __align__(16) float g_g[(size_t)N_NODES * DCAT];
__device__ float g_z[(size_t)N_NODES * 20];

#define CP_ASYNC16(dst, src) \
    asm volatile("cp.async.cg.shared.global [%0], [%1], 16;" :: "r"(dst), "l"(src))
#define CP_COMMIT() asm volatile("cp.async.commit_group;" ::: "memory")
#define CP_WAIT0()  asm volatile("cp.async.wait_group 0;" ::: "memory")

__device__ __forceinline__ uint32_t smem_u32(const void* p) {
    uint32_t a;
    asm("{ .reg .u64 t; cvta.to.shared.u64 t, %1; cvt.u32.u64 %0, t; }" : "=r"(a) : "l"(p));
    return a;
}

// ---------------- dtype detect ------------------------------------------------
__global__ void k_detect(const int* __restrict__ ei32) {
    if (threadIdx.x == 0) {
        int odd_nonzero = 0;
        for (int i = 0; i < 64; i++) odd_nonzero |= ei32[2 * i + 1];
        g_is64 = (odd_nonzero == 0) ? 1 : 0;
    }
}
__device__ __forceinline__ int edge_row(const int* ei32, int e, int is64) {
    return is64 ? ei32[2 * e] : ei32[e];
}
__device__ __forceinline__ int edge_col(const int* ei32, int e, int is64) {
    return is64 ? ei32[2 * (N_EDGES + e)] : ei32[N_EDGES + e];
}

// ---------------- CSR build ---------------------------------------------------
__global__ void k_zero() {
    int i = blockIdx.x * blockDim.x + threadIdx.x;
    if (i < N_NODES) { g_counts[i] = 0; g_cursor[i] = 0; }
}
__global__ void k_hist(const int* __restrict__ ei32) {
    int e = blockIdx.x * blockDim.x + threadIdx.x;
    if (e < N_EDGES) {
        int r = edge_row(ei32, e, g_is64);
        if ((unsigned)r < N_NODES) atomicAdd(&g_counts[r], 1);
    }
}
__global__ void k_scan1() {
    __shared__ int sm[256];
    int i = blockIdx.x * 256 + threadIdx.x;
    sm[threadIdx.x] = (i < N_NODES) ? g_counts[i] : 0;
    __syncthreads();
    for (int off = 128; off; off >>= 1) {
        if (threadIdx.x < off) sm[threadIdx.x] += sm[threadIdx.x + off];
        __syncthreads();
    }
    if (threadIdx.x == 0) g_blockSums[blockIdx.x] = sm[0];
}
__global__ void k_scan2(int nblocks) {
    __shared__ int sm[256];
    int v = (threadIdx.x < nblocks) ? g_blockSums[threadIdx.x] : 0;
    sm[threadIdx.x] = v;
    __syncthreads();
    for (int off = 1; off < 256; off <<= 1) {
        int t = (threadIdx.x >= off) ? sm[threadIdx.x - off] : 0;
        __syncthreads();
        sm[threadIdx.x] += t;
        __syncthreads();
    }
    if (threadIdx.x < nblocks) g_blockOffs[threadIdx.x] = sm[threadIdx.x] - v;
    if (threadIdx.x == 255) g_row_start[N_NODES] = sm[255];
}
__global__ void k_scan3() {
    __shared__ int sm[256];
    int i = blockIdx.x * 256 + threadIdx.x;
    int v = (i < N_NODES) ? g_counts[i] : 0;
    sm[threadIdx.x] = v;
    __syncthreads();
    for (int off = 1; off < 256; off <<= 1) {
        int t = (threadIdx.x >= off) ? sm[threadIdx.x - off] : 0;
        __syncthreads();
        sm[threadIdx.x] += t;
        __syncthreads();
    }
    if (i < N_NODES) g_row_start[i] = g_blockOffs[blockIdx.x] + sm[threadIdx.x] - v;
}
__global__ void k_scatter(const int* __restrict__ ei32, const float* __restrict__ ew) {
    int e = blockIdx.x * blockDim.x + threadIdx.x;
    if (e < N_EDGES) {
        int is64 = g_is64;
        int r = edge_row(ei32, e, is64);
        int c = edge_col(ei32, e, is64);
        if ((unsigned)r < N_NODES && (unsigned)c < N_NODES) {
            int p = g_row_start[r] + atomicAdd(&g_cursor[r], 1);
            g_col[p] = c;
            g_w[p]   = ew[e];
        }
    }
}

// ---------------- prep: x -> fp16, w -> fp16 hi/lo -----------------------------
__global__ void k_prep_x(const float* __restrict__ x) {
    int t  = blockIdx.x * 256 + threadIdx.x;
    int r  = t >> 7;
    int c0 = (t & 127) * 4;
    if (r >= MPAD) return;
    float4 v = make_float4(0.f, 0.f, 0.f, 0.f);
    if (r < N_NODES && c0 < N_FEAT)
        v = *(const float4*)(x + (size_t)r * N_FEAT + c0);
    __half h[4];
    h[0] = __float2half_rn(v.x); h[1] = __float2half_rn(v.y);
    h[2] = __float2half_rn(v.z); h[3] = __float2half_rn(v.w);
    *(uint2*)(g_xh + (size_t)r * KPAD + c0) = *(uint2*)h;
}
__global__ void k_prep_w(const float* __restrict__ W1a, const float* __restrict__ b1a,
                         const float* __restrict__ W1b, const float* __restrict__ b1b) {
    int t = blockIdx.x * 256 + threadIdx.x;
    if (t >= DCAT * KPAD) return;
    int n = t >> 9, k = t & 511;
    float v = 0.f;
    if (k < N_FEAT)
        v = (n < N_HID) ? W1a[k * N_HID + n] : W1b[k * N_HID + (n - N_HID)];
    __half h = __float2half_rn(v);
    g_whT[n * KPAD + k] = h;
    g_wlT[n * KPAD + k] = __float2half_rn(v - __half2float(h));
    if (t < DCAT) g_bcat[t] = (t < N_HID) ? b1a[t] : b1b[t - N_HID];
}

// ---------------- GEMM1 (fp16 2-term: y = xh*(wh+wl)), cp.async ---------------
#define BM 128
#define BN 128
#define BK 16
#define PITCH 24

__device__ __forceinline__ void mma16816(float* c, const unsigned* a, const unsigned* b) {
    asm volatile(
        "mma.sync.aligned.m16n8k16.row.col.f32.f16.f16.f32 "
        "{%0,%1,%2,%3}, {%4,%5,%6,%7}, {%8,%9}, {%0,%1,%2,%3};\n"
        : "+f"(c[0]), "+f"(c[1]), "+f"(c[2]), "+f"(c[3])
        : "r"(a[0]), "r"(a[1]), "r"(a[2]), "r"(a[3]), "r"(b[0]), "r"(b[1]));
}

__global__ void __launch_bounds__(256, 2) k_gemm1_mma() {
    __shared__ __align__(16) __half sAh[2][BM * PITCH];
    __shared__ __align__(16) __half sBh[2][BN * PITCH];
    __shared__ __align__(16) __half sBl[2][BN * PITCH];

    const int tid  = threadIdx.x;
    const int bm   = blockIdx.y * BM;
    const int bn   = blockIdx.x * BN;
    const int wid  = tid >> 5, lane = tid & 31;
    const int wm   = wid & 1, wn = wid >> 1;
    const int mw   = wm * 64, nw = wn * 32;
    const int gid  = lane >> 2;
    const int tk4  = lane & 3;

    const int lr = tid >> 1;
    const int lk = (tid & 1) * 8;
    const size_t aoff = (size_t)(bm + lr) * KPAD + lk;
    const size_t boff = (size_t)(bn + lr) * KPAD + lk;
    const uint32_t sAh0 = smem_u32(&sAh[0][0]);
    const uint32_t sBh0 = smem_u32(&sBh[0][0]);
    const uint32_t sBl0 = smem_u32(&sBl[0][0]);
    const uint32_t soffB = (lr * PITCH + lk) * 2;
    const uint32_t stageB = BM * PITCH * 2;

    float acc[16][4];
#pragma unroll
    for (int i = 0; i < 16; i++)
#pragma unroll
        for (int j = 0; j < 4; j++) acc[i][j] = 0.f;

    CP_ASYNC16(sAh0 + soffB, g_xh + aoff);
    CP_ASYNC16(sBh0 + soffB, g_whT + boff);
    CP_ASYNC16(sBl0 + soffB, g_wlT + boff);
    CP_COMMIT();
    CP_WAIT0();
    __syncthreads();

    const int NSTAGE = KPAD / BK;  // 32
    for (int s = 0; s < NSTAGE; s++) {
        const int cur = s & 1, nxt = cur ^ 1;
        if (s + 1 < NSTAGE) {
            int k0 = (s + 1) * BK;
            uint32_t so = nxt * stageB + soffB;
            CP_ASYNC16(sAh0 + so, g_xh + aoff + k0);
            CP_ASYNC16(sBh0 + so, g_whT + boff + k0);
            CP_ASYNC16(sBl0 + so, g_wlT + boff + k0);
            CP_COMMIT();
        }

        unsigned Ah[4][4], Bh[4][2], Bl[4][2];
#pragma unroll
        for (int ni = 0; ni < 4; ni++) {
            int n = nw + ni * 8 + gid;
            Bh[ni][0] = *(const unsigned*)&sBh[cur][n * PITCH + tk4 * 2];
            Bh[ni][1] = *(const unsigned*)&sBh[cur][n * PITCH + tk4 * 2 + 8];
            Bl[ni][0] = *(const unsigned*)&sBl[cur][n * PITCH + tk4 * 2];
            Bl[ni][1] = *(const unsigned*)&sBl[cur][n * PITCH + tk4 * 2 + 8];
        }
#pragma unroll
        for (int mi = 0; mi < 4; mi++) {
            int m = mw + mi * 16 + gid;
            Ah[mi][0] = *(const unsigned*)&sAh[cur][m * PITCH + tk4 * 2];
            Ah[mi][1] = *(const unsigned*)&sAh[cur][(m + 8) * PITCH + tk4 * 2];
            Ah[mi][2] = *(const unsigned*)&sAh[cur][m * PITCH + tk4 * 2 + 8];
            Ah[mi][3] = *(const unsigned*)&sAh[cur][(m + 8) * PITCH + tk4 * 2 + 8];
        }
#pragma unroll
        for (int mi = 0; mi < 4; mi++)
#pragma unroll
            for (int ni = 0; ni < 4; ni++) {
                mma16816(acc[mi * 4 + ni], Ah[mi], Bh[ni]);
                mma16816(acc[mi * 4 + ni], Ah[mi], Bl[ni]);
            }

        if (s + 1 < NSTAGE) CP_WAIT0();
        __syncthreads();
    }

    // epilogue: bias add in fp32, store fp16
#pragma unroll
    for (int mi = 0; mi < 4; mi++) {
#pragma unroll
        for (int ni = 0; ni < 4; ni++) {
            int r = bm + mw + mi * 16 + gid;
            int c = bn + nw + ni * 8 + tk4 * 2;
            float b0 = g_bcat[c], b1 = g_bcat[c + 1];
            float* acc4 = acc[mi * 4 + ni];
            __half2 h0 = __floats2half2_rn(acc4[0] + b0, acc4[1] + b1);
            __half2 h1 = __floats2half2_rn(acc4[2] + b0, acc4[3] + b1);
            *reinterpret_cast<__half2*>(&g_yh[(size_t)r * DCAT + c]) = h0;
            *reinterpret_cast<__half2*>(&g_yh[(size_t)(r + 8) * DCAT + c]) = h1;
        }
    }
}

// ---------------- SpMM1: g[row] = relu( sum_e w * yh[col] ), D=512 ------------
__global__ void __launch_bounds__(128) k_spmm1() {
    int row = blockIdx.x;
    int s = g_row_start[row], t = g_row_start[row + 1];
    int d = threadIdx.x * 4;
    float ax = 0.f, ay = 0.f, az = 0.f, aw = 0.f;
    for (int e = s; e < t; e++) {
        int   c = __ldg(&g_col[e]);
        float w = __ldg(&g_w[e]);
        uint2 v = *(const uint2*)(g_yh + (size_t)c * DCAT + d);
        float2 f0 = __half22float2(*reinterpret_cast<__half2*>(&v.x));
        float2 f1 = __half22float2(*reinterpret_cast<__half2*>(&v.y));
        ax += w * f0.x; ay += w * f0.y; az += w * f1.x; aw += w * f1.y;
    }
    float4 o;
    o.x = fmaxf(ax, 0.f); o.y = fmaxf(ay, 0.f);
    o.z = fmaxf(az, 0.f); o.w = fmaxf(aw, 0.f);
    *(float4*)&g_g[(size_t)row * DCAT + d] = o;
}

// ---------------- GEMM2 -------------------------------------------------------
__global__ void __launch_bounds__(256) k_gemm2(
    const float* __restrict__ W2a, const float* __restrict__ b2a,
    const float* __restrict__ W2b, const float* __restrict__ b2b)
{
    __shared__ float sW[DCAT * 10];
    for (int i = threadIdx.x; i < DCAT * 10; i += blockDim.x) {
        int d = i / 10, c = i % 10;
        sW[i] = (d < N_HID) ? W2a[d * 10 + c] : W2b[(d - N_HID) * 10 + c];
    }
    __syncthreads();

    int lane   = threadIdx.x & 31;
    int warp   = (blockIdx.x * blockDim.x + threadIdx.x) >> 5;
    int nwarps = (gridDim.x * blockDim.x) >> 5;

    for (int row = warp; row < N_NODES; row += nwarps) {
        float acc[20];
#pragma unroll
        for (int c = 0; c < 20; c++) acc[c] = 0.f;
        const float* grow = &g_g[(size_t)row * DCAT];
#pragma unroll
        for (int k = 0; k < 16; k++) {
            int d = lane + 32 * k;
            float gv = grow[d];
            const float* wrow = &sW[d * 10];
            float* ap = (k < 8) ? acc : acc + 10;
#pragma unroll
            for (int c = 0; c < 10; c++) ap[c] += gv * wrow[c];
        }
#pragma unroll
        for (int c = 0; c < 20; c++) {
            float v = acc[c];
            v += __shfl_xor_sync(0xffffffffu, v, 16);
            v += __shfl_xor_sync(0xffffffffu, v, 8);
            v += __shfl_xor_sync(0xffffffffu, v, 4);
            v += __shfl_xor_sync(0xffffffffu, v, 2);
            v += __shfl_xor_sync(0xffffffffu, v, 1);
            acc[c] = v;
        }
        if (lane == 0) {
#pragma unroll
            for (int c = 0; c < 10; c++) g_z[(size_t)row * 20 + c]      = acc[c]      + b2a[c];
#pragma unroll
            for (int c = 0; c < 10; c++) g_z[(size_t)row * 20 + 10 + c] = acc[10 + c] + b2b[c];
        }
    }
}

// ---------------- SpMM2: 320 threads = 16 rows x 20 lanes ---------------------
__global__ void __launch_bounds__(320) k_spmm2(float* __restrict__ out) {
    int t    = threadIdx.x;
    int row  = blockIdx.x * 16 + t / 20;
    int c20  = t % 20;
    if (row >= N_NODES) return;
    int s = g_row_start[row], tend = g_row_start[row + 1];
    float acc = 0.f;
    for (int e = s; e < tend; e++) {
        int   c = __ldg(&g_col[e]);
        float w = __ldg(&g_w[e]);
        acc += w * g_z[(size_t)c * 20 + c20];
    }
    int br = c20 / 10, cc = c20 % 10;
    out[(size_t)br * (N_NODES * N_CLASS) + (size_t)row * N_CLASS + cc] = acc;
}

// ---------------- launch ------------------------------------------------------
extern "C" void kernel_launch(void* const* d_in, const int* in_sizes, int n_in,
                              void* d_out, int out_size)
{
    const float* x   = (const float*)d_in[0];
    const int*   ei  = (const int*)d_in[1];
    const float* ew  = (const float*)d_in[2];
    const float* W1a = (const float*)d_in[3];
    const float* b1a = (const float*)d_in[4];
    const float* W2a = (const float*)d_in[5];
    const float* b2a = (const float*)d_in[6];
    const float* W1b = (const float*)d_in[7];
    const float* b1b = (const float*)d_in[8];
    const float* W2b = (const float*)d_in[9];
    const float* b2b = (const float*)d_in[10];
    float* out = (float*)d_out;

    const int SCAN_BLOCKS = (N_NODES + 255) / 256;  // 196

    k_detect<<<1, 32>>>(ei);
    k_zero<<<(N_NODES + 255) / 256, 256>>>();
    k_hist<<<(N_EDGES + 255) / 256, 256>>>(ei);
    k_scan1<<<SCAN_BLOCKS, 256>>>();
    k_scan2<<<1, 256>>>(SCAN_BLOCKS);
    k_scan3<<<SCAN_BLOCKS, 256>>>();
    k_scatter<<<(N_EDGES + 255) / 256, 256>>>(ei, ew);
    k_prep_x<<<(MPAD * 128 + 255) / 256, 256>>>(x);
    k_prep_w<<<(DCAT * KPAD + 255) / 256, 256>>>(W1a, b1a, W1b, b1b);
    k_gemm1_mma<<<dim3(DCAT / BN, MPAD / BM), 256>>>();
    k_spmm1<<<N_NODES, 128>>>();
    k_gemm2<<<782, 256>>>(W2a, b2a, W2b, b2b);
    k_spmm2<<<(N_NODES + 15) / 16, 320>>>(out);
}

// round 13
// speedup vs baseline: 1.7966x; 1.1774x over previous
#include <cuda_runtime.h>
#include <cuda_fp16.h>
#include <cstdint>

#define N_NODES 50000
#define N_EDGES 800000
#define N_FEAT  500
#define N_HID   256
#define DCAT    512   // fused hidden width (2 branches x 256)
#define N_CLASS 10
#define MPAD    50048 // 391 * 128
#define KPAD    512

// ---------------- device scratch ----------------------------------------------
__device__ int   g_is64;
__device__ int   g_counts[N_NODES];
__device__ int   g_row_start[N_NODES + 1];
__device__ int   g_cursor[N_NODES];
__device__ int   g_blockSums[256];
__device__ int   g_blockOffs[256];
__device__ int   g_col[N_EDGES];
__device__ float g_w[N_EDGES];
__device__ __align__(16) __half g_xh[(size_t)MPAD * KPAD];   // fp16(x)
__device__ __align__(16) __half g_whT[DCAT * KPAD];          // [n][k] fp16(w)
__device__ float g_bcat[DCAT];
__device__ __align__(16) __half g_yh[(size_t)MPAD * DCAT];   // y in fp16
__device__ __align__(16) __half g_gh[(size_t)N_NODES * DCAT];// relu(spmm(y)) fp16
__device__ float g_z[(size_t)N_NODES * 20];

#define CP_ASYNC16(dst, src) \
    asm volatile("cp.async.cg.shared.global [%0], [%1], 16;" :: "r"(dst), "l"(src))
#define CP_COMMIT() asm volatile("cp.async.commit_group;" ::: "memory")
#define CP_WAIT0()  asm volatile("cp.async.wait_group 0;" ::: "memory")

__device__ __forceinline__ uint32_t smem_u32(const void* p) {
    uint32_t a;
    asm("{ .reg .u64 t; cvta.to.shared.u64 t, %1; cvt.u32.u64 %0, t; }" : "=r"(a) : "l"(p));
    return a;
}

// ---------------- dtype detect ------------------------------------------------
__global__ void k_detect(const int* __restrict__ ei32) {
    if (threadIdx.x == 0) {
        int odd_nonzero = 0;
        for (int i = 0; i < 64; i++) odd_nonzero |= ei32[2 * i + 1];
        g_is64 = (odd_nonzero == 0) ? 1 : 0;
    }
}
__device__ __forceinline__ int edge_row(const int* ei32, int e, int is64) {
    return is64 ? ei32[2 * e] : ei32[e];
}
__device__ __forceinline__ int edge_col(const int* ei32, int e, int is64) {
    return is64 ? ei32[2 * (N_EDGES + e)] : ei32[N_EDGES + e];
}

// ---------------- CSR build ---------------------------------------------------
__global__ void k_zero() {
    int i = blockIdx.x * blockDim.x + threadIdx.x;
    if (i < N_NODES) { g_counts[i] = 0; g_cursor[i] = 0; }
}
__global__ void k_hist(const int* __restrict__ ei32) {
    int e = blockIdx.x * blockDim.x + threadIdx.x;
    if (e < N_EDGES) {
        int r = edge_row(ei32, e, g_is64);
        if ((unsigned)r < N_NODES) atomicAdd(&g_counts[r], 1);
    }
}
__global__ void k_scan1() {
    __shared__ int sm[256];
    int i = blockIdx.x * 256 + threadIdx.x;
    sm[threadIdx.x] = (i < N_NODES) ? g_counts[i] : 0;
    __syncthreads();
    for (int off = 128; off; off >>= 1) {
        if (threadIdx.x < off) sm[threadIdx.x] += sm[threadIdx.x + off];
        __syncthreads();
    }
    if (threadIdx.x == 0) g_blockSums[blockIdx.x] = sm[0];
}
__global__ void k_scan2(int nblocks) {
    __shared__ int sm[256];
    int v = (threadIdx.x < nblocks) ? g_blockSums[threadIdx.x] : 0;
    sm[threadIdx.x] = v;
    __syncthreads();
    for (int off = 1; off < 256; off <<= 1) {
        int t = (threadIdx.x >= off) ? sm[threadIdx.x - off] : 0;
        __syncthreads();
        sm[threadIdx.x] += t;
        __syncthreads();
    }
    if (threadIdx.x < nblocks) g_blockOffs[threadIdx.x] = sm[threadIdx.x] - v;
    if (threadIdx.x == 255) g_row_start[N_NODES] = sm[255];
}
__global__ void k_scan3() {
    __shared__ int sm[256];
    int i = blockIdx.x * 256 + threadIdx.x;
    int v = (i < N_NODES) ? g_counts[i] : 0;
    sm[threadIdx.x] = v;
    __syncthreads();
    for (int off = 1; off < 256; off <<= 1) {
        int t = (threadIdx.x >= off) ? sm[threadIdx.x - off] : 0;
        __syncthreads();
        sm[threadIdx.x] += t;
        __syncthreads();
    }
    if (i < N_NODES) g_row_start[i] = g_blockOffs[blockIdx.x] + sm[threadIdx.x] - v;
}
__global__ void k_scatter(const int* __restrict__ ei32, const float* __restrict__ ew) {
    int e = blockIdx.x * blockDim.x + threadIdx.x;
    if (e < N_EDGES) {
        int is64 = g_is64;
        int r = edge_row(ei32, e, is64);
        int c = edge_col(ei32, e, is64);
        if ((unsigned)r < N_NODES && (unsigned)c < N_NODES) {
            int p = g_row_start[r] + atomicAdd(&g_cursor[r], 1);
            g_col[p] = c;
            g_w[p]   = ew[e];
        }
    }
}

// ---------------- prep: x -> fp16, w -> fp16 -----------------------------------
__global__ void k_prep_x(const float* __restrict__ x) {
    int t  = blockIdx.x * 256 + threadIdx.x;
    int r  = t >> 7;
    int c0 = (t & 127) * 4;
    if (r >= MPAD) return;
    float4 v = make_float4(0.f, 0.f, 0.f, 0.f);
    if (r < N_NODES && c0 < N_FEAT)
        v = *(const float4*)(x + (size_t)r * N_FEAT + c0);
    __half h[4];
    h[0] = __float2half_rn(v.x); h[1] = __float2half_rn(v.y);
    h[2] = __float2half_rn(v.z); h[3] = __float2half_rn(v.w);
    *(uint2*)(g_xh + (size_t)r * KPAD + c0) = *(uint2*)h;
}
__global__ void k_prep_w(const float* __restrict__ W1a, const float* __restrict__ b1a,
                         const float* __restrict__ W1b, const float* __restrict__ b1b) {
    int t = blockIdx.x * 256 + threadIdx.x;
    if (t >= DCAT * KPAD) return;
    int n = t >> 9, k = t & 511;
    float v = 0.f;
    if (k < N_FEAT)
        v = (n < N_HID) ? W1a[k * N_HID + n] : W1b[k * N_HID + (n - N_HID)];
    g_whT[n * KPAD + k] = __float2half_rn(v);
    if (t < DCAT) g_bcat[t] = (t < N_HID) ? b1a[t] : b1b[t - N_HID];
}

// ---------------- GEMM1 (fp16 single-term: y = xh*wh), cp.async ---------------
#define BM 128
#define BN 128
#define BK 16
#define PITCH 24

__device__ __forceinline__ void mma16816(float* c, const unsigned* a, const unsigned* b) {
    asm volatile(
        "mma.sync.aligned.m16n8k16.row.col.f32.f16.f16.f32 "
        "{%0,%1,%2,%3}, {%4,%5,%6,%7}, {%8,%9}, {%0,%1,%2,%3};\n"
        : "+f"(c[0]), "+f"(c[1]), "+f"(c[2]), "+f"(c[3])
        : "r"(a[0]), "r"(a[1]), "r"(a[2]), "r"(a[3]), "r"(b[0]), "r"(b[1]));
}

__global__ void __launch_bounds__(256, 2) k_gemm1_mma() {
    __shared__ __align__(16) __half sAh[2][BM * PITCH];
    __shared__ __align__(16) __half sBh[2][BN * PITCH];

    const int tid  = threadIdx.x;
    const int bm   = blockIdx.y * BM;
    const int bn   = blockIdx.x * BN;
    const int wid  = tid >> 5, lane = tid & 31;
    const int wm   = wid & 1, wn = wid >> 1;
    const int mw   = wm * 64, nw = wn * 32;
    const int gid  = lane >> 2;
    const int tk4  = lane & 3;

    const int lr = tid >> 1;
    const int lk = (tid & 1) * 8;
    const size_t aoff = (size_t)(bm + lr) * KPAD + lk;
    const size_t boff = (size_t)(bn + lr) * KPAD + lk;
    const uint32_t sAh0 = smem_u32(&sAh[0][0]);
    const uint32_t sBh0 = smem_u32(&sBh[0][0]);
    const uint32_t soffB = (lr * PITCH + lk) * 2;
    const uint32_t stageB = BM * PITCH * 2;

    float acc[16][4];
#pragma unroll
    for (int i = 0; i < 16; i++)
#pragma unroll
        for (int j = 0; j < 4; j++) acc[i][j] = 0.f;

    CP_ASYNC16(sAh0 + soffB, g_xh + aoff);
    CP_ASYNC16(sBh0 + soffB, g_whT + boff);
    CP_COMMIT();
    CP_WAIT0();
    __syncthreads();

    const int NSTAGE = KPAD / BK;  // 32
    for (int s = 0; s < NSTAGE; s++) {
        const int cur = s & 1, nxt = cur ^ 1;
        if (s + 1 < NSTAGE) {
            int k0 = (s + 1) * BK;
            uint32_t so = nxt * stageB + soffB;
            CP_ASYNC16(sAh0 + so, g_xh + aoff + k0);
            CP_ASYNC16(sBh0 + so, g_whT + boff + k0);
            CP_COMMIT();
        }

        unsigned Ah[4][4], Bh[4][2];
#pragma unroll
        for (int ni = 0; ni < 4; ni++) {
            int n = nw + ni * 8 + gid;
            Bh[ni][0] = *(const unsigned*)&sBh[cur][n * PITCH + tk4 * 2];
            Bh[ni][1] = *(const unsigned*)&sBh[cur][n * PITCH + tk4 * 2 + 8];
        }
#pragma unroll
        for (int mi = 0; mi < 4; mi++) {
            int m = mw + mi * 16 + gid;
            Ah[mi][0] = *(const unsigned*)&sAh[cur][m * PITCH + tk4 * 2];
            Ah[mi][1] = *(const unsigned*)&sAh[cur][(m + 8) * PITCH + tk4 * 2];
            Ah[mi][2] = *(const unsigned*)&sAh[cur][m * PITCH + tk4 * 2 + 8];
            Ah[mi][3] = *(const unsigned*)&sAh[cur][(m + 8) * PITCH + tk4 * 2 + 8];
        }
#pragma unroll
        for (int mi = 0; mi < 4; mi++)
#pragma unroll
            for (int ni = 0; ni < 4; ni++)
                mma16816(acc[mi * 4 + ni], Ah[mi], Bh[ni]);

        if (s + 1 < NSTAGE) CP_WAIT0();
        __syncthreads();
    }

    // epilogue: bias add in fp32, store fp16
#pragma unroll
    for (int mi = 0; mi < 4; mi++) {
#pragma unroll
        for (int ni = 0; ni < 4; ni++) {
            int r = bm + mw + mi * 16 + gid;
            int c = bn + nw + ni * 8 + tk4 * 2;
            float b0 = g_bcat[c], b1 = g_bcat[c + 1];
            float* acc4 = acc[mi * 4 + ni];
            __half2 h0 = __floats2half2_rn(acc4[0] + b0, acc4[1] + b1);
            __half2 h1 = __floats2half2_rn(acc4[2] + b0, acc4[3] + b1);
            *reinterpret_cast<__half2*>(&g_yh[(size_t)r * DCAT + c]) = h0;
            *reinterpret_cast<__half2*>(&g_yh[(size_t)(r + 8) * DCAT + c]) = h1;
        }
    }
}

// ---------------- SpMM1: gh[row] = relu( sum_e w * yh[col] ), D=512 -----------
__global__ void __launch_bounds__(128) k_spmm1() {
    int row = blockIdx.x;
    int s = g_row_start[row], t = g_row_start[row + 1];
    int d = threadIdx.x * 4;
    float ax = 0.f, ay = 0.f, az = 0.f, aw = 0.f;
    for (int e = s; e < t; e++) {
        int   c = __ldg(&g_col[e]);
        float w = __ldg(&g_w[e]);
        uint2 v = *(const uint2*)(g_yh + (size_t)c * DCAT + d);
        float2 f0 = __half22float2(*reinterpret_cast<__half2*>(&v.x));
        float2 f1 = __half22float2(*reinterpret_cast<__half2*>(&v.y));
        ax += w * f0.x; ay += w * f0.y; az += w * f1.x; aw += w * f1.y;
    }
    __half2 o0 = __floats2half2_rn(fmaxf(ax, 0.f), fmaxf(ay, 0.f));
    __half2 o1 = __floats2half2_rn(fmaxf(az, 0.f), fmaxf(aw, 0.f));
    uint2 o; o.x = *reinterpret_cast<uint32_t*>(&o0); o.y = *reinterpret_cast<uint32_t*>(&o1);
    *(uint2*)(g_gh + (size_t)row * DCAT + d) = o;
}

// ---------------- GEMM2 (fp16 g input) ----------------------------------------
__global__ void __launch_bounds__(256) k_gemm2(
    const float* __restrict__ W2a, const float* __restrict__ b2a,
    const float* __restrict__ W2b, const float* __restrict__ b2b)
{
    __shared__ float sW[DCAT * 10];
    for (int i = threadIdx.x; i < DCAT * 10; i += blockDim.x) {
        int d = i / 10, c = i % 10;
        sW[i] = (d < N_HID) ? W2a[d * 10 + c] : W2b[(d - N_HID) * 10 + c];
    }
    __syncthreads();

    int lane   = threadIdx.x & 31;
    int warp   = (blockIdx.x * blockDim.x + threadIdx.x) >> 5;
    int nwarps = (gridDim.x * blockDim.x) >> 5;

    for (int row = warp; row < N_NODES; row += nwarps) {
        float acc[20];
#pragma unroll
        for (int c = 0; c < 20; c++) acc[c] = 0.f;
        const __half* grow = &g_gh[(size_t)row * DCAT];
#pragma unroll
        for (int k = 0; k < 8; k++) {           // k<4 -> branch 1, k>=4 -> branch 2
            int d0 = 64 * k + 2 * lane;
            __half2 hv = *reinterpret_cast<const __half2*>(grow + d0);
            float2 f = __half22float2(hv);
            const float* w0 = &sW[d0 * 10];
            const float* w1 = &sW[(d0 + 1) * 10];
            float* ap = (k < 4) ? acc : acc + 10;
#pragma unroll
            for (int c = 0; c < 10; c++) ap[c] += f.x * w0[c] + f.y * w1[c];
        }
#pragma unroll
        for (int c = 0; c < 20; c++) {
            float v = acc[c];
            v += __shfl_xor_sync(0xffffffffu, v, 16);
            v += __shfl_xor_sync(0xffffffffu, v, 8);
            v += __shfl_xor_sync(0xffffffffu, v, 4);
            v += __shfl_xor_sync(0xffffffffu, v, 2);
            v += __shfl_xor_sync(0xffffffffu, v, 1);
            acc[c] = v;
        }
        if (lane == 0) {
#pragma unroll
            for (int c = 0; c < 10; c++) g_z[(size_t)row * 20 + c]      = acc[c]      + b2a[c];
#pragma unroll
            for (int c = 0; c < 10; c++) g_z[(size_t)row * 20 + 10 + c] = acc[10 + c] + b2b[c];
        }
    }
}

// ---------------- SpMM2: 320 threads = 16 rows x 20 lanes ---------------------
__global__ void __launch_bounds__(320) k_spmm2(float* __restrict__ out) {
    int t    = threadIdx.x;
    int row  = blockIdx.x * 16 + t / 20;
    int c20  = t % 20;
    if (row >= N_NODES) return;
    int s = g_row_start[row], tend = g_row_start[row + 1];
    float acc = 0.f;
    for (int e = s; e < tend; e++) {
        int   c = __ldg(&g_col[e]);
        float w = __ldg(&g_w[e]);
        acc += w * g_z[(size_t)c * 20 + c20];
    }
    int br = c20 / 10, cc = c20 % 10;
    out[(size_t)br * (N_NODES * N_CLASS) + (size_t)row * N_CLASS + cc] = acc;
}

// ---------------- launch ------------------------------------------------------
extern "C" void kernel_launch(void* const* d_in, const int* in_sizes, int n_in,
                              void* d_out, int out_size)
{
    const float* x   = (const float*)d_in[0];
    const int*   ei  = (const int*)d_in[1];
    const float* ew  = (const float*)d_in[2];
    const float* W1a = (const float*)d_in[3];
    const float* b1a = (const float*)d_in[4];
    const float* W2a = (const float*)d_in[5];
    const float* b2a = (const float*)d_in[6];
    const float* W1b = (const float*)d_in[7];
    const float* b1b = (const float*)d_in[8];
    const float* W2b = (const float*)d_in[9];
    const float* b2b = (const float*)d_in[10];
    float* out = (float*)d_out;

    const int SCAN_BLOCKS = (N_NODES + 255) / 256;  // 196

    k_detect<<<1, 32>>>(ei);
    k_zero<<<(N_NODES + 255) / 256, 256>>>();
    k_hist<<<(N_EDGES + 255) / 256, 256>>>(ei);
    k_scan1<<<SCAN_BLOCKS, 256>>>();
    k_scan2<<<1, 256>>>(SCAN_BLOCKS);
    k_scan3<<<SCAN_BLOCKS, 256>>>();
    k_scatter<<<(N_EDGES + 255) / 256, 256>>>(ei, ew);
    k_prep_x<<<(MPAD * 128 + 255) / 256, 256>>>(x);
    k_prep_w<<<(DCAT * KPAD + 255) / 256, 256>>>(W1a, b1a, W1b, b1b);
    k_gemm1_mma<<<dim3(DCAT / BN, MPAD / BM), 256>>>();
    k_spmm1<<<N_NODES, 128>>>();
    k_gemm2<<<782, 256>>>(W2a, b2a, W2b, b2b);
    k_spmm2<<<(N_NODES + 15) / 16, 320>>>(out);
}